// round 14
// baseline (speedup 1.0000x reference)
#include <cuda_runtime.h>
#include <cuda_bf16.h>
#include <cstdint>

// Problem constants
#define NTOK 256
#define CZ   128
#define CH   32
#define NH   4
#define NROW (NTOK*NTOK)        // 65536 tokens
#define INV_SQRT_C 0.17677669529663688f

// ---------------- scratch (device globals; no allocation allowed) -------------
__device__ float g_zn[NROW*CZ];            // layernormed z        [row][128]
__device__ float g_qkvg[4][NROW*CZ];       // q,k,v,g              [row][h*32+c]
__device__ float g_bK[NH*NROW];            // bias+maskbias, TRANSPOSED: [h][k*256+j]
__device__ float g_o[NROW*CZ];             // attention out (pre-gate)

// ---------------- packed f32x2 helpers (sm_103a FFMA2 path) ------------------
__device__ __forceinline__ unsigned long long pk2(float x, float y) {
    unsigned long long d;
    asm("mov.b64 %0, {%1, %2};" : "=l"(d) : "f"(x), "f"(y));
    return d;
}
__device__ __forceinline__ float2 upk2(unsigned long long v) {
    float2 r;
    asm("mov.b64 {%0, %1}, %2;" : "=f"(r.x), "=f"(r.y) : "l"(v));
    return r;
}
__device__ __forceinline__ unsigned long long fma2(unsigned long long a,
                                                   unsigned long long b,
                                                   unsigned long long c) {
    unsigned long long d;
    asm("fma.rn.f32x2 %0, %1, %2, %3;" : "=l"(d) : "l"(a), "l"(b), "l"(c));
    return d;
}
__device__ __forceinline__ unsigned long long add2(unsigned long long a,
                                                   unsigned long long b) {
    unsigned long long d;
    asm("add.rn.f32x2 %0, %1, %2;" : "=l"(d) : "l"(a), "l"(b));
    return d;
}
__device__ __forceinline__ unsigned long long mul2(unsigned long long a,
                                                   unsigned long long b) {
    unsigned long long d;
    asm("mul.rn.f32x2 %0, %1, %2;" : "=l"(d) : "l"(a), "l"(b));
    return d;
}

// ======================== 1. LayerNorm + b projection (warp per row) ==========
__global__ void __launch_bounds__(256) ln_kernel(
    const float* __restrict__ z, const float* __restrict__ gamma,
    const float* __restrict__ beta, const float* __restrict__ Wb,
    const float* __restrict__ mask)
{
    int wid  = threadIdx.x >> 5;
    int lane = threadIdx.x & 31;
    int r    = blockIdx.x * 8 + wid;          // row 0..65535

    float4 x4 = ((const float4*)&z[r*CZ])[lane];
    float s  = (x4.x + x4.y) + (x4.z + x4.w);
    float s2 = fmaf(x4.x, x4.x, fmaf(x4.y, x4.y, fmaf(x4.z, x4.z, x4.w*x4.w)));
    #pragma unroll
    for (int o = 16; o > 0; o >>= 1) {
        s  += __shfl_xor_sync(0xffffffffu, s,  o);
        s2 += __shfl_xor_sync(0xffffffffu, s2, o);
    }
    float mu  = s  * (1.0f/CZ);
    float var = s2 * (1.0f/CZ) - mu*mu;
    float inv = rsqrtf(var + 1e-5f);

    float4 g4 = ((const float4*)gamma)[lane];
    float4 b4 = ((const float4*)beta)[lane];
    float zn[4];
    zn[0] = (x4.x - mu)*inv*g4.x + b4.x;
    zn[1] = (x4.y - mu)*inv*g4.y + b4.y;
    zn[2] = (x4.z - mu)*inv*g4.z + b4.z;
    zn[3] = (x4.w - mu)*inv*g4.w + b4.w;
    float4 znv = make_float4(zn[0], zn[1], zn[2], zn[3]);
    ((float4*)&g_zn[r*CZ])[lane] = znv;

    float p0 = 0.f, p1 = 0.f, p2 = 0.f, p3 = 0.f;
    #pragma unroll
    for (int u = 0; u < 4; u++) {
        float4 w = ((const float4*)Wb)[lane*4 + u];   // Wb[c][0..3]
        p0 = fmaf(zn[u], w.x, p0);
        p1 = fmaf(zn[u], w.y, p1);
        p2 = fmaf(zn[u], w.z, p2);
        p3 = fmaf(zn[u], w.w, p3);
    }
    #pragma unroll
    for (int o = 16; o > 0; o >>= 1) {
        p0 += __shfl_xor_sync(0xffffffffu, p0, o);
        p1 += __shfl_xor_sync(0xffffffffu, p1, o);
        p2 += __shfl_xor_sync(0xffffffffu, p2, o);
        p3 += __shfl_xor_sync(0xffffffffu, p3, o);
    }
    if (lane == 0) {
        int j = r >> 8, k = r & (NTOK-1);
        float mb = -1e9f * (1.0f - mask[k]);
        int idx = k*NTOK + j;                  // transposed
        g_bK[0*NROW + idx] = p0 + mb;
        g_bK[1*NROW + idx] = p1 + mb;
        g_bK[2*NROW + idx] = p2 + mb;
        g_bK[3*NROW + idx] = p3 + mb;
    }
}

// ======================== 2. projection GEMM (FFMA2, N-packed, dup-A, lean) ===
// g_qkvg[buf][65536,128] = g_zn[65536,128] @ W[128,128], buf = blockIdx.y
// block tile 64x128; 256 threads: ty=tid>>4 -> rows ty*4..ty*4+3,
// tx=tid&15 -> col-pairs 2*tx+32n.  A duplicated in smem (float2) so the
// broadcast operand is one LDS.64; accumulators packed along N.
#define LDA2 66   // float2 stride (pad to soften STS conflicts)
__global__ void __launch_bounds__(256) proj_gemm(
    const float* __restrict__ Wq, const float* __restrict__ Wk,
    const float* __restrict__ Wv, const float* __restrict__ Wg)
{
    __shared__ __align__(16) float2 Ad[16][LDA2];  // 8.25 KB
    __shared__ __align__(16) float  Bs[16][128];   // 8 KB
    int row0 = blockIdx.x * 64;
    int buf  = blockIdx.y;
    const float* W = (buf == 0) ? Wq : (buf == 1) ? Wk : (buf == 2) ? Wv : Wg;
    int tid = threadIdx.x;
    int tx = tid & 15;     // col-pair group
    int ty = tid >> 4;     // row group: rows ty*4..ty*4+3

    unsigned long long acc2[4][4];
    #pragma unroll
    for (int p = 0; p < 4; p++)
        #pragma unroll
        for (int n = 0; n < 4; n++) acc2[p][n] = 0ull;

    int ar  = tid >> 2;    // 0..63 (A row)
    int ac4 = tid & 3;     // float4 within 16-k

    for (int k0 = 0; k0 < 128; k0 += 16) {
        {   // A: 64 rows x 16 k, dup-stored (one float4 per thread)
            float4 a = *(const float4*)&g_zn[(row0+ar)*CZ + k0 + ac4*4];
            Ad[ac4*4+0][ar] = make_float2(a.x, a.x);
            Ad[ac4*4+1][ar] = make_float2(a.y, a.y);
            Ad[ac4*4+2][ar] = make_float2(a.z, a.z);
            Ad[ac4*4+3][ar] = make_float2(a.w, a.w);
        }
        #pragma unroll
        for (int l = 0; l < 2; l++) {          // B: 16 k x 128 n
            int e = tid + 256*l, bk = e >> 5, bc = e & 31;
            *(float4*)&Bs[bk][bc*4] = *(const float4*)&W[(k0+bk)*128 + bc*4];
        }
        __syncthreads();
        #pragma unroll
        for (int kk = 0; kk < 16; kk++) {
            unsigned long long a2[4], b2[4];
            #pragma unroll
            for (int p = 0; p < 4; p++)
                a2[p] = *(const unsigned long long*)&Ad[kk][ty*4 + p];
            #pragma unroll
            for (int n = 0; n < 4; n++)
                b2[n] = *(const unsigned long long*)&Bs[kk][2*tx + 32*n];
            #pragma unroll
            for (int p = 0; p < 4; p++)
                #pragma unroll
                for (int n = 0; n < 4; n++)
                    acc2[p][n] = fma2(a2[p], b2[n], acc2[p][n]);
        }
        __syncthreads();
    }

    #pragma unroll
    for (int p = 0; p < 4; p++) {
        int row = row0 + ty*4 + p;
        #pragma unroll
        for (int n = 0; n < 4; n++)
            *(unsigned long long*)&g_qkvg[buf][row*CZ + 2*tx + 32*n] = acc2[p][n];
    }
}

// ======================== 3. attention (flash-style, FFMA2, double-buffered) ==
#define KC 32
__global__ void __launch_bounds__(256) attn_kernel()
{
    int i = blockIdx.x, h = blockIdx.y;
    int t = threadIdx.x;

    __shared__ __align__(16) float Ks[2][KC][32];     // 8 KB
    __shared__ __align__(16) float Vs[2][KC][32];     // 8 KB

    unsigned long long q2[16];
    {
        const float4* qb = (const float4*)&g_qkvg[0][(i*NTOK + t)*CZ + h*CH];
        #pragma unroll
        for (int m = 0; m < 8; m++) {
            float4 v = qb[m];
            q2[2*m+0] = pk2(v.x * INV_SQRT_C, v.y * INV_SQRT_C);
            q2[2*m+1] = pk2(v.z * INV_SQRT_C, v.w * INV_SQRT_C);
        }
    }

    unsigned long long o2[16];
    #pragma unroll
    for (int m = 0; m < 16; m++) o2[m] = 0ull;
    float sum = 0.f;

    int kr = t >> 3, f4i = t & 7;
    const float* bK = &g_bK[h*NROW + t];
    const float* kbase = &g_qkvg[1][i*NTOK*CZ + h*CH + f4i*4];
    const float* vbase = &g_qkvg[2][i*NTOK*CZ + h*CH + f4i*4];

    {
        float4 rk = *(const float4*)&kbase[kr*CZ];
        float4 rv = *(const float4*)&vbase[kr*CZ];
        *(float4*)&Ks[0][kr][f4i*4] = rk;
        *(float4*)&Vs[0][kr][f4i*4] = rv;
    }
    __syncthreads();

    for (int c8 = 0; c8 < 8; c8++) {
        int buf = c8 & 1;
        int k0  = c8 * KC;

        float4 rk, rv;
        if (c8 < 7) {
            rk = *(const float4*)&kbase[(k0 + KC + kr)*CZ];
            rv = *(const float4*)&vbase[(k0 + KC + kr)*CZ];
        }

        #pragma unroll
        for (int g = 0; g < 8; g++) {
            float bias[4];
            #pragma unroll
            for (int u = 0; u < 4; u++)
                bias[u] = bK[(k0 + g*4 + u)*NTOK];
            #pragma unroll
            for (int u = 0; u < 4; u++) {
                int kk = g*4 + u;
                const ulonglong2* kp = (const ulonglong2*)&Ks[buf][kk][0];
                unsigned long long a0 = 0ull, a1 = 0ull;
                #pragma unroll
                for (int p = 0; p < 4; p++) {
                    ulonglong2 kv = kp[p];
                    a0 = fma2(q2[2*p+0], kv.x, a0);
                    a1 = fma2(q2[2*p+1], kv.y, a1);
                }
                const ulonglong2* kp2 = (const ulonglong2*)&Ks[buf][kk][16];
                #pragma unroll
                for (int p = 0; p < 4; p++) {
                    ulonglong2 kv = kp2[p];
                    a0 = fma2(q2[8+2*p+0], kv.x, a0);
                    a1 = fma2(q2[8+2*p+1], kv.y, a1);
                }
                unsigned long long at = add2(a0, a1);
                float2 f = upk2(at);
                float s = bias[u] + (f.x + f.y);
                float p = __expf(s);
                sum += p;
                unsigned long long pp = pk2(p, p);
                const ulonglong2* vp = (const ulonglong2*)&Vs[buf][kk][0];
                #pragma unroll
                for (int m = 0; m < 4; m++) {
                    ulonglong2 vv = vp[m];
                    o2[2*m+0] = fma2(pp, vv.x, o2[2*m+0]);
                    o2[2*m+1] = fma2(pp, vv.y, o2[2*m+1]);
                }
                const ulonglong2* vp2 = (const ulonglong2*)&Vs[buf][kk][16];
                #pragma unroll
                for (int m = 0; m < 4; m++) {
                    ulonglong2 vv = vp2[m];
                    o2[8+2*m+0] = fma2(pp, vv.x, o2[8+2*m+0]);
                    o2[8+2*m+1] = fma2(pp, vv.y, o2[8+2*m+1]);
                }
            }
        }

        if (c8 < 7) {
            *(float4*)&Ks[buf^1][kr][f4i*4] = rk;
            *(float4*)&Vs[buf^1][kr][f4i*4] = rv;
        }
        __syncthreads();
    }

    float inv = 1.0f / sum;
    unsigned long long iv = pk2(inv, inv);
    float* orow = &g_o[(i*NTOK + t)*CZ + h*CH];
    #pragma unroll
    for (int m = 0; m < 8; m++) {
        ulonglong2 st;
        st.x = mul2(o2[2*m+0], iv);
        st.y = mul2(o2[2*m+1], iv);
        *(ulonglong2*)&orow[m*4] = st;
    }
}

// ======================== 4. gated output GEMM (FFMA2, N-packed, dup-A, lean) =
// out[65536,128] = (sigmoid(g)*o)[65536,128] @ W_out[128,128]
__global__ void __launch_bounds__(256) out_gemm(const float* __restrict__ Wout,
                                               float* __restrict__ out)
{
    __shared__ __align__(16) float2 Ad[16][LDA2];  // 8.25 KB
    __shared__ __align__(16) float  Bs[16][128];   // 8 KB
    int row0 = blockIdx.x * 64;
    int tid = threadIdx.x;
    int tx = tid & 15;
    int ty = tid >> 4;

    unsigned long long acc2[4][4];
    #pragma unroll
    for (int p = 0; p < 4; p++)
        #pragma unroll
        for (int n = 0; n < 4; n++) acc2[p][n] = 0ull;

    int ar  = tid >> 2;
    int ac4 = tid & 3;

    for (int k0 = 0; k0 < 128; k0 += 16) {
        {   // gated A tile 64x16, dup-stored
            float4 o4 = *(const float4*)&g_o      [(row0+ar)*CZ + k0 + ac4*4];
            float4 gg = *(const float4*)&g_qkvg[3][(row0+ar)*CZ + k0 + ac4*4];
            float a0 = o4.x / (1.0f + __expf(-gg.x));
            float a1 = o4.y / (1.0f + __expf(-gg.y));
            float a2v = o4.z / (1.0f + __expf(-gg.z));
            float a3 = o4.w / (1.0f + __expf(-gg.w));
            Ad[ac4*4+0][ar] = make_float2(a0, a0);
            Ad[ac4*4+1][ar] = make_float2(a1, a1);
            Ad[ac4*4+2][ar] = make_float2(a2v, a2v);
            Ad[ac4*4+3][ar] = make_float2(a3, a3);
        }
        #pragma unroll
        for (int l = 0; l < 2; l++) {
            int e = tid + 256*l, bk = e >> 5, bc = e & 31;
            *(float4*)&Bs[bk][bc*4] = *(const float4*)&Wout[(k0+bk)*128 + bc*4];
        }
        __syncthreads();
        #pragma unroll
        for (int kk = 0; kk < 16; kk++) {
            unsigned long long a2[4], b2[4];
            #pragma unroll
            for (int p = 0; p < 4; p++)
                a2[p] = *(const unsigned long long*)&Ad[kk][ty*4 + p];
            #pragma unroll
            for (int n = 0; n < 4; n++)
                b2[n] = *(const unsigned long long*)&Bs[kk][2*tx + 32*n];
            #pragma unroll
            for (int p = 0; p < 4; p++)
                #pragma unroll
                for (int n = 0; n < 4; n++)
                    acc2[p][n] = fma2(a2[p], b2[n], acc2[p][n]);
        }
        __syncthreads();
    }

    #pragma unroll
    for (int p = 0; p < 4; p++) {
        int row = row0 + ty*4 + p;
        #pragma unroll
        for (int n = 0; n < 4; n++)
            *(unsigned long long*)&out[row*CZ + 2*tx + 32*n] = acc2[p][n];
    }
}

// ======================== launch ============================================
extern "C" void kernel_launch(void* const* d_in, const int* in_sizes, int n_in,
                              void* d_out, int out_size)
{
    const float* z     = (const float*)d_in[0];
    const float* smask = (const float*)d_in[1];
    const float* gam   = (const float*)d_in[2];
    const float* bet   = (const float*)d_in[3];
    const float* Wq    = (const float*)d_in[4];
    const float* Wk    = (const float*)d_in[5];
    const float* Wv    = (const float*)d_in[6];
    const float* Wb    = (const float*)d_in[7];
    const float* Wg    = (const float*)d_in[8];
    const float* Wout  = (const float*)d_in[9];
    float* out = (float*)d_out;

    ln_kernel<<<NROW/8, 256>>>(z, gam, bet, Wb, smask);
    proj_gemm<<<dim3(NROW/64, 4), 256>>>(Wq, Wk, Wv, Wg);
    attn_kernel<<<dim3(NTOK, NH), 256>>>();
    out_gemm<<<NROW/64, 256>>>(Wout, out);
}

// round 15
// speedup vs baseline: 1.1104x; 1.1104x over previous
#include <cuda_runtime.h>
#include <cuda_bf16.h>
#include <cstdint>

// Problem constants
#define NTOK 256
#define CZ   128
#define CH   32
#define NH   4
#define NROW (NTOK*NTOK)        // 65536 tokens
#define INV_SQRT_C 0.17677669529663688f

// ---------------- scratch (device globals; no allocation allowed) -------------
__device__ float g_zn[NROW*CZ];            // layernormed z        [row][128]
__device__ float g_qkvg[4][NROW*CZ];       // q,k,v,g              [row][h*32+c]
// bias+maskbias, GROUPED: [h][k>>2][j][k&3]  (4 keys of a group contiguous)
__device__ float g_bK[NH*NROW];
__device__ float g_o[NROW*CZ];             // attention out (pre-gate)

// ---------------- packed f32x2 helpers (sm_103a FFMA2 path) ------------------
__device__ __forceinline__ unsigned long long pk2(float x, float y) {
    unsigned long long d;
    asm("mov.b64 %0, {%1, %2};" : "=l"(d) : "f"(x), "f"(y));
    return d;
}
__device__ __forceinline__ float2 upk2(unsigned long long v) {
    float2 r;
    asm("mov.b64 {%0, %1}, %2;" : "=f"(r.x), "=f"(r.y) : "l"(v));
    return r;
}
__device__ __forceinline__ unsigned long long fma2(unsigned long long a,
                                                   unsigned long long b,
                                                   unsigned long long c) {
    unsigned long long d;
    asm("fma.rn.f32x2 %0, %1, %2, %3;" : "=l"(d) : "l"(a), "l"(b), "l"(c));
    return d;
}
__device__ __forceinline__ unsigned long long add2(unsigned long long a,
                                                   unsigned long long b) {
    unsigned long long d;
    asm("add.rn.f32x2 %0, %1, %2;" : "=l"(d) : "l"(a), "l"(b));
    return d;
}
__device__ __forceinline__ unsigned long long mul2(unsigned long long a,
                                                   unsigned long long b) {
    unsigned long long d;
    asm("mul.rn.f32x2 %0, %1, %2;" : "=l"(d) : "l"(a), "l"(b));
    return d;
}

// ======================== 1. LayerNorm + b projection (warp per row) ==========
// Bias stored grouped-by-4-keys: g_bK[h*NROW + (k>>2)*1024 + j*4 + (k&3)]
__global__ void __launch_bounds__(256) ln_kernel(
    const float* __restrict__ z, const float* __restrict__ gamma,
    const float* __restrict__ beta, const float* __restrict__ Wb,
    const float* __restrict__ mask)
{
    int wid  = threadIdx.x >> 5;
    int lane = threadIdx.x & 31;
    int r    = blockIdx.x * 8 + wid;          // row 0..65535

    float4 x4 = ((const float4*)&z[r*CZ])[lane];
    float s  = (x4.x + x4.y) + (x4.z + x4.w);
    float s2 = fmaf(x4.x, x4.x, fmaf(x4.y, x4.y, fmaf(x4.z, x4.z, x4.w*x4.w)));
    #pragma unroll
    for (int o = 16; o > 0; o >>= 1) {
        s  += __shfl_xor_sync(0xffffffffu, s,  o);
        s2 += __shfl_xor_sync(0xffffffffu, s2, o);
    }
    float mu  = s  * (1.0f/CZ);
    float var = s2 * (1.0f/CZ) - mu*mu;
    float inv = rsqrtf(var + 1e-5f);

    float4 g4 = ((const float4*)gamma)[lane];
    float4 b4 = ((const float4*)beta)[lane];
    float zn[4];
    zn[0] = (x4.x - mu)*inv*g4.x + b4.x;
    zn[1] = (x4.y - mu)*inv*g4.y + b4.y;
    zn[2] = (x4.z - mu)*inv*g4.z + b4.z;
    zn[3] = (x4.w - mu)*inv*g4.w + b4.w;
    float4 znv = make_float4(zn[0], zn[1], zn[2], zn[3]);
    ((float4*)&g_zn[r*CZ])[lane] = znv;

    float p0 = 0.f, p1 = 0.f, p2 = 0.f, p3 = 0.f;
    #pragma unroll
    for (int u = 0; u < 4; u++) {
        float4 w = ((const float4*)Wb)[lane*4 + u];   // Wb[c][0..3]
        p0 = fmaf(zn[u], w.x, p0);
        p1 = fmaf(zn[u], w.y, p1);
        p2 = fmaf(zn[u], w.z, p2);
        p3 = fmaf(zn[u], w.w, p3);
    }
    #pragma unroll
    for (int o = 16; o > 0; o >>= 1) {
        p0 += __shfl_xor_sync(0xffffffffu, p0, o);
        p1 += __shfl_xor_sync(0xffffffffu, p1, o);
        p2 += __shfl_xor_sync(0xffffffffu, p2, o);
        p3 += __shfl_xor_sync(0xffffffffu, p3, o);
    }
    if (lane == 0) {
        int j = r >> 8, k = r & (NTOK-1);
        float mb = -1e9f * (1.0f - mask[k]);
        int idx = (k >> 2)*(NTOK*4) + j*4 + (k & 3);   // grouped layout
        g_bK[0*NROW + idx] = p0 + mb;
        g_bK[1*NROW + idx] = p1 + mb;
        g_bK[2*NROW + idx] = p2 + mb;
        g_bK[3*NROW + idx] = p3 + mb;
    }
}

// ======================== 2. projection GEMM (FFMA2) =========================
// g_qkvg[buf][65536,128] = g_zn[65536,128] @ W[128,128], buf = blockIdx.y
__global__ void __launch_bounds__(256) proj_gemm(
    const float* __restrict__ Wq, const float* __restrict__ Wk,
    const float* __restrict__ Wv, const float* __restrict__ Wg)
{
    __shared__ __align__(16) float As[16][64];
    __shared__ __align__(16) float Bs[16][128];
    int row0 = blockIdx.x * 64;
    int buf  = blockIdx.y;
    const float* W = (buf == 0) ? Wq : (buf == 1) ? Wk : (buf == 2) ? Wv : Wg;
    int tid  = threadIdx.x;
    int tx = tid & 31;     // col group 0..31
    int ty = tid >> 5;     // row group 0..7 (rows ty*8 .. ty*8+7)

    unsigned long long acc2[4][4];
    #pragma unroll
    for (int p = 0; p < 4; p++)
        #pragma unroll
        for (int ni = 0; ni < 4; ni++) acc2[p][ni] = 0ull;

    int ar  = tid >> 2;    // 0..63  (A row)
    int akv = tid & 3;     // 0..3   (A float4 within 16)

    for (int k0 = 0; k0 < 128; k0 += 16) {
        float4 a = *(const float4*)&g_zn[(row0+ar)*CZ + k0 + akv*4];
        As[akv*4+0][ar] = a.x; As[akv*4+1][ar] = a.y;
        As[akv*4+2][ar] = a.z; As[akv*4+3][ar] = a.w;
        #pragma unroll
        for (int l = 0; l < 2; l++) {
            int e = tid + 256*l;        // 512 float4 slots
            int bk = e >> 5, bc = e & 31;
            *(float4*)&Bs[bk][bc*4] = *(const float4*)&W[(k0+bk)*128 + bc*4];
        }
        __syncthreads();
        #pragma unroll
        for (int kk = 0; kk < 16; kk++) {
            unsigned long long a2[4];
            #pragma unroll
            for (int p = 0; p < 4; p++)
                a2[p] = *(const unsigned long long*)&As[kk][ty*8 + 2*p];
            #pragma unroll
            for (int ni = 0; ni < 4; ni++) {
                float bv = Bs[kk][tx + 32*ni];
                unsigned long long b2 = pk2(bv, bv);
                #pragma unroll
                for (int p = 0; p < 4; p++)
                    acc2[p][ni] = fma2(a2[p], b2, acc2[p][ni]);
            }
        }
        __syncthreads();
    }

    #pragma unroll
    for (int p = 0; p < 4; p++) {
        int row = row0 + ty*8 + 2*p;
        #pragma unroll
        for (int ni = 0; ni < 4; ni++) {
            int n = tx + 32*ni;
            float2 f = upk2(acc2[p][ni]);
            g_qkvg[buf][row*CZ + n]       = f.x;
            g_qkvg[buf][(row+1)*CZ + n]   = f.y;
        }
    }
}

// ======================== 3. attention (flash-style, FFMA2, double-buffered) ==
// one block per (i, h); 256 threads; thread t owns QUERY row j = t.
// Bias read as ONE LDG.128 per 4-key group (grouped layout), prefetched
// one group ahead.  K/V chunks double-buffered via registers (R11 scheme).
#define KC 32
__global__ void __launch_bounds__(256) attn_kernel()
{
    int i = blockIdx.x, h = blockIdx.y;
    int t = threadIdx.x;

    __shared__ __align__(16) float Ks[2][KC][32];     // 8 KB
    __shared__ __align__(16) float Vs[2][KC][32];     // 8 KB

    unsigned long long q2[16];
    {
        const float4* qb = (const float4*)&g_qkvg[0][(i*NTOK + t)*CZ + h*CH];
        #pragma unroll
        for (int m = 0; m < 8; m++) {
            float4 v = qb[m];
            q2[2*m+0] = pk2(v.x * INV_SQRT_C, v.y * INV_SQRT_C);
            q2[2*m+1] = pk2(v.z * INV_SQRT_C, v.w * INV_SQRT_C);
        }
    }

    unsigned long long o2[16];
    #pragma unroll
    for (int m = 0; m < 16; m++) o2[m] = 0ull;
    float sum = 0.f;

    int kr = t >> 3, f4i = t & 7;
    // bias float4 pointer: group gi (0..63) at bB[gi*256 + t]
    const float4* bB = (const float4*)&g_bK[h*NROW];
    const float* kbase = &g_qkvg[1][i*NTOK*CZ + h*CH + f4i*4];
    const float* vbase = &g_qkvg[2][i*NTOK*CZ + h*CH + f4i*4];

    // preload chunk 0 into buffer 0; prefetch bias group 0
    {
        float4 rk = *(const float4*)&kbase[kr*CZ];
        float4 rv = *(const float4*)&vbase[kr*CZ];
        *(float4*)&Ks[0][kr][f4i*4] = rk;
        *(float4*)&Vs[0][kr][f4i*4] = rv;
    }
    float4 bcur = bB[t];     // group 0
    __syncthreads();

    for (int c8 = 0; c8 < 8; c8++) {
        int buf = c8 & 1;
        int k0  = c8 * KC;

        float4 rk, rv;
        if (c8 < 7) {
            rk = *(const float4*)&kbase[(k0 + KC + kr)*CZ];
            rv = *(const float4*)&vbase[(k0 + KC + kr)*CZ];
        }

        #pragma unroll
        for (int g = 0; g < 8; g++) {
            int gi = c8*8 + g;
            // prefetch next group's bias (one coalesced LDG.128)
            float4 bnext;
            if (gi < 63) bnext = bB[(gi+1)*256 + t];
            float bias[4] = {bcur.x, bcur.y, bcur.z, bcur.w};
            #pragma unroll
            for (int u = 0; u < 4; u++) {
                int kk = g*4 + u;
                const ulonglong2* kp = (const ulonglong2*)&Ks[buf][kk][0];
                unsigned long long a0 = 0ull, a1 = 0ull;
                #pragma unroll
                for (int p = 0; p < 4; p++) {
                    ulonglong2 kv = kp[p];
                    a0 = fma2(q2[2*p+0], kv.x, a0);
                    a1 = fma2(q2[2*p+1], kv.y, a1);
                }
                const ulonglong2* kp2 = (const ulonglong2*)&Ks[buf][kk][16];
                #pragma unroll
                for (int p = 0; p < 4; p++) {
                    ulonglong2 kv = kp2[p];
                    a0 = fma2(q2[8+2*p+0], kv.x, a0);
                    a1 = fma2(q2[8+2*p+1], kv.y, a1);
                }
                unsigned long long at = add2(a0, a1);
                float2 f = upk2(at);
                float s = bias[u] + (f.x + f.y);
                float p = __expf(s);
                sum += p;
                unsigned long long pp = pk2(p, p);
                const ulonglong2* vp = (const ulonglong2*)&Vs[buf][kk][0];
                #pragma unroll
                for (int m = 0; m < 4; m++) {
                    ulonglong2 vv = vp[m];
                    o2[2*m+0] = fma2(pp, vv.x, o2[2*m+0]);
                    o2[2*m+1] = fma2(pp, vv.y, o2[2*m+1]);
                }
                const ulonglong2* vp2 = (const ulonglong2*)&Vs[buf][kk][16];
                #pragma unroll
                for (int m = 0; m < 4; m++) {
                    ulonglong2 vv = vp2[m];
                    o2[8+2*m+0] = fma2(pp, vv.x, o2[8+2*m+0]);
                    o2[8+2*m+1] = fma2(pp, vv.y, o2[8+2*m+1]);
                }
            }
            if (gi < 63) bcur = bnext;
        }

        if (c8 < 7) {
            *(float4*)&Ks[buf^1][kr][f4i*4] = rk;
            *(float4*)&Vs[buf^1][kr][f4i*4] = rv;
        }
        __syncthreads();
    }

    float inv = 1.0f / sum;
    unsigned long long iv = pk2(inv, inv);
    float* orow = &g_o[(i*NTOK + t)*CZ + h*CH];
    #pragma unroll
    for (int m = 0; m < 8; m++) {
        ulonglong2 st;
        st.x = mul2(o2[2*m+0], iv);
        st.y = mul2(o2[2*m+1], iv);
        *(ulonglong2*)&orow[m*4] = st;
    }
}

// ======================== 4. gated output GEMM (FFMA2) =======================
// out[65536,128] = (sigmoid(g)*o)[65536,128] @ W_out[128,128]
__global__ void __launch_bounds__(256) out_gemm(const float* __restrict__ Wout,
                                               float* __restrict__ out)
{
    __shared__ __align__(16) float As[16][64];
    __shared__ __align__(16) float Bs[16][128];
    int row0 = blockIdx.x * 64;
    int tid  = threadIdx.x;
    int tx = tid & 31;
    int ty = tid >> 5;

    unsigned long long acc2[4][4];
    #pragma unroll
    for (int p = 0; p < 4; p++)
        #pragma unroll
        for (int ni = 0; ni < 4; ni++) acc2[p][ni] = 0ull;

    int ar  = tid >> 2;
    int akv = tid & 3;

    for (int k0 = 0; k0 < 128; k0 += 16) {
        float4 o4 = *(const float4*)&g_o      [(row0+ar)*CZ + k0 + akv*4];
        float4 gg = *(const float4*)&g_qkvg[3][(row0+ar)*CZ + k0 + akv*4];
        As[akv*4+0][ar] = o4.x / (1.0f + __expf(-gg.x));
        As[akv*4+1][ar] = o4.y / (1.0f + __expf(-gg.y));
        As[akv*4+2][ar] = o4.z / (1.0f + __expf(-gg.z));
        As[akv*4+3][ar] = o4.w / (1.0f + __expf(-gg.w));
        #pragma unroll
        for (int l = 0; l < 2; l++) {
            int e = tid + 256*l;
            int bk = e >> 5, bc = e & 31;
            *(float4*)&Bs[bk][bc*4] = *(const float4*)&Wout[(k0+bk)*128 + bc*4];
        }
        __syncthreads();
        #pragma unroll
        for (int kk = 0; kk < 16; kk++) {
            unsigned long long a2[4];
            #pragma unroll
            for (int p = 0; p < 4; p++)
                a2[p] = *(const unsigned long long*)&As[kk][ty*8 + 2*p];
            #pragma unroll
            for (int ni = 0; ni < 4; ni++) {
                float bv = Bs[kk][tx + 32*ni];
                unsigned long long b2 = pk2(bv, bv);
                #pragma unroll
                for (int p = 0; p < 4; p++)
                    acc2[p][ni] = fma2(a2[p], b2, acc2[p][ni]);
            }
        }
        __syncthreads();
    }

    #pragma unroll
    for (int p = 0; p < 4; p++) {
        int row = row0 + ty*8 + 2*p;
        #pragma unroll
        for (int ni = 0; ni < 4; ni++) {
            int n = tx + 32*ni;
            float2 f = upk2(acc2[p][ni]);
            out[row*CZ + n]     = f.x;
            out[(row+1)*CZ + n] = f.y;
        }
    }
}

// ======================== launch ============================================
extern "C" void kernel_launch(void* const* d_in, const int* in_sizes, int n_in,
                              void* d_out, int out_size)
{
    const float* z     = (const float*)d_in[0];
    const float* smask = (const float*)d_in[1];
    const float* gam   = (const float*)d_in[2];
    const float* bet   = (const float*)d_in[3];
    const float* Wq    = (const float*)d_in[4];
    const float* Wk    = (const float*)d_in[5];
    const float* Wv    = (const float*)d_in[6];
    const float* Wb    = (const float*)d_in[7];
    const float* Wg    = (const float*)d_in[8];
    const float* Wout  = (const float*)d_in[9];
    float* out = (float*)d_out;

    ln_kernel<<<NROW/8, 256>>>(z, gam, bet, Wb, smask);
    proj_gemm<<<dim3(NROW/64, 4), 256>>>(Wq, Wk, Wv, Wg);
    attn_kernel<<<dim3(NTOK, NH), 256>>>();
    out_gemm<<<NROW/64, 256>>>(Wout, out);
}